// round 1
// baseline (speedup 1.0000x reference)
#include <cuda_runtime.h>

#define BM 128
#define BN 128
#define BK 16

// Scratch (allocation-free rule: __device__ globals)
__device__ float g_t [8192u * 1024u];   // intermediate t = x @ V^T (32 MB)
__device__ float g_Us[4096u * 1024u];   // (U concat) * s        (16 MB)
__device__ float g_V [1024u * 4096u];   // V concat              (16 MB)

// Build Us[o][r] = s[r] * cat(U_t,U_d)[o][r]  and  V[r][i] = cat(V_t,V_d)[r][i]
__global__ void pack_kernel(const float* __restrict__ u_t, const float* __restrict__ u_d,
                            const float* __restrict__ s,
                            const float* __restrict__ v_t, const float* __restrict__ v_d)
{
    int idx = blockIdx.x * blockDim.x + threadIdx.x;
    if (idx < 4096 * 1024) {
        int o = idx >> 10, r = idx & 1023;
        float u = (r < 64) ? u_t[o * 64 + r] : u_d[o * 960 + (r - 64)];
        g_Us[idx] = u * s[r];
    } else {
        int j = idx - 4096 * 1024;       // j = r*4096 + i
        int r = j >> 12;
        g_V[j] = (r < 64) ? v_t[j] : v_d[j - (64 << 12)];
    }
}

// C[M,N] = A[M,K] * B[N,K]^T (+ bias[n]).  M%128==0, N%128==0, K%16==0.
template<bool BIAS>
__global__ __launch_bounds__(256, 2)
void gemm_tn(const float* __restrict__ A, const float* __restrict__ B,
             const float* __restrict__ bias, float* __restrict__ C,
             int M, int N, int K)
{
    __shared__ __align__(16) float As[BK][BM + 4];   // +4 floats = 16B -> row stride stays 16B-aligned
    __shared__ __align__(16) float Bs[BK][BN + 4];

    const int tid = threadIdx.x;
    const int tx = tid & 15;
    const int ty = tid >> 4;

    const int rowBase = blockIdx.y * BM;
    const int colBase = blockIdx.x * BN;
    const int KT = K / BK;

    const float* Ag = A + (long)rowBase * K;
    const float* Bg = B + (long)colBase * K;

    float c[8][8];
#pragma unroll
    for (int i = 0; i < 8; i++)
#pragma unroll
        for (int j = 0; j < 8; j++) c[i][j] = 0.f;

    // Each thread loads 2 float4 per tile per matrix: rows r0 and r0+64, k-offset k4.
    const int r0 = tid >> 2;            // 0..63
    const int r1 = r0 + 64;             // 64..127
    const int k4 = (tid & 3) * 4;       // 0,4,8,12

    // ---- preload tile 0 ----
    float4 pa0 = *(const float4*)(Ag + (long)r0 * K + k4);
    float4 pa1 = *(const float4*)(Ag + (long)r1 * K + k4);
    float4 pb0 = *(const float4*)(Bg + (long)r0 * K + k4);
    float4 pb1 = *(const float4*)(Bg + (long)r1 * K + k4);

    As[k4 + 0][r0] = pa0.x; As[k4 + 1][r0] = pa0.y; As[k4 + 2][r0] = pa0.z; As[k4 + 3][r0] = pa0.w;
    As[k4 + 0][r1] = pa1.x; As[k4 + 1][r1] = pa1.y; As[k4 + 2][r1] = pa1.z; As[k4 + 3][r1] = pa1.w;
    Bs[k4 + 0][r0] = pb0.x; Bs[k4 + 1][r0] = pb0.y; Bs[k4 + 2][r0] = pb0.z; Bs[k4 + 3][r0] = pb0.w;
    Bs[k4 + 0][r1] = pb1.x; Bs[k4 + 1][r1] = pb1.y; Bs[k4 + 2][r1] = pb1.z; Bs[k4 + 3][r1] = pb1.w;
    __syncthreads();

    for (int kt = 0; kt < KT; kt++) {
        const bool more = (kt + 1 < KT);
        if (more) {
            const float* An = Ag + (long)(kt + 1) * BK;
            const float* Bn = Bg + (long)(kt + 1) * BK;
            pa0 = *(const float4*)(An + (long)r0 * K + k4);
            pa1 = *(const float4*)(An + (long)r1 * K + k4);
            pb0 = *(const float4*)(Bn + (long)r0 * K + k4);
            pb1 = *(const float4*)(Bn + (long)r1 * K + k4);
        }

#pragma unroll
        for (int k = 0; k < BK; k++) {
            float a[8], b[8];
            *(float4*)(a    ) = *(const float4*)&As[k][ty * 4];
            *(float4*)(a + 4) = *(const float4*)&As[k][64 + ty * 4];
            *(float4*)(b    ) = *(const float4*)&Bs[k][tx * 4];
            *(float4*)(b + 4) = *(const float4*)&Bs[k][64 + tx * 4];
#pragma unroll
            for (int i = 0; i < 8; i++)
#pragma unroll
                for (int j = 0; j < 8; j++)
                    c[i][j] = fmaf(a[i], b[j], c[i][j]);
        }
        __syncthreads();

        if (more) {
            As[k4 + 0][r0] = pa0.x; As[k4 + 1][r0] = pa0.y; As[k4 + 2][r0] = pa0.z; As[k4 + 3][r0] = pa0.w;
            As[k4 + 0][r1] = pa1.x; As[k4 + 1][r1] = pa1.y; As[k4 + 2][r1] = pa1.z; As[k4 + 3][r1] = pa1.w;
            Bs[k4 + 0][r0] = pb0.x; Bs[k4 + 1][r0] = pb0.y; Bs[k4 + 2][r0] = pb0.z; Bs[k4 + 3][r0] = pb0.w;
            Bs[k4 + 0][r1] = pb1.x; Bs[k4 + 1][r1] = pb1.y; Bs[k4 + 2][r1] = pb1.z; Bs[k4 + 3][r1] = pb1.w;
            __syncthreads();
        }
    }

    // ---- epilogue ----
#pragma unroll
    for (int i = 0; i < 8; i++) {
        const int row = rowBase + ((i < 4) ? (ty * 4 + i) : (64 + ty * 4 + (i - 4)));
        float* Crow = C + (long)row * N + colBase;
#pragma unroll
        for (int h = 0; h < 2; h++) {
            const int col = h * 64 + tx * 4;
            float4 v = make_float4(c[i][h * 4 + 0], c[i][h * 4 + 1],
                                   c[i][h * 4 + 2], c[i][h * 4 + 3]);
            if (BIAS) {
                float4 bv = *(const float4*)(bias + colBase + col);
                v.x += bv.x; v.y += bv.y; v.z += bv.z; v.w += bv.w;
            }
            *(float4*)(Crow + col) = v;
        }
    }
}

extern "C" void kernel_launch(void* const* d_in, const int* in_sizes, int n_in,
                              void* d_out, int out_size)
{
    const float* x    = (const float*)d_in[0];   // [4,2048,4096]
    const float* u_t  = (const float*)d_in[1];   // [4096,64]
    const float* u_d  = (const float*)d_in[2];   // [4096,960]
    const float* s    = (const float*)d_in[3];   // [1024]
    const float* v_t  = (const float*)d_in[4];   // [64,4096]
    const float* v_d  = (const float*)d_in[5];   // [960,4096]
    const float* bias = (const float*)d_in[6];   // [4096]
    float* out = (float*)d_out;                  // [4,2048,4096]

    (void)in_sizes; (void)n_in; (void)out_size;

    float *tbuf, *Us, *V;
    cudaGetSymbolAddress((void**)&tbuf, g_t);
    cudaGetSymbolAddress((void**)&Us,   g_Us);
    cudaGetSymbolAddress((void**)&V,    g_V);

    // 1) pack Us = cat(U_t,U_d)*s  and  V = cat(V_t,V_d)
    pack_kernel<<<(8u * 1024u * 1024u) / 256u, 256>>>(u_t, u_d, s, v_t, v_d);

    const int M = 8192;
    // 2) t = x @ V^T          (M=8192, N=1024, K=4096)
    gemm_tn<false><<<dim3(1024 / BN, M / BM), 256>>>(x, V, nullptr, tbuf, M, 1024, 4096);
    // 3) out = t @ Us^T + bias (M=8192, N=4096, K=1024)
    gemm_tn<true ><<<dim3(4096 / BN, M / BM), 256>>>(tbuf, Us, bias, out, M, 4096, 1024);
}

// round 3
// speedup vs baseline: 2.4445x; 2.4445x over previous
#include <cuda_runtime.h>
#include <cstdint>

// ---------------- tiles ----------------
#define BM 128
#define BN 128
#define BK 16
#define STAGES 4
#define SA 20                            // padded float stride (conflict-free frag reads)
#define AS_FLOATS (BM * SA)              // 2560 floats per A stage
#define STAGE_FLOATS (2 * AS_FLOATS)     // A + B
#define SMEM_BYTES (STAGES * STAGE_FLOATS * 4)   // 81920

// ---------------- scratch (allocation-free rule) ----------------
__device__ __align__(1024) float g_xt[33554432];  // x, tf32-rounded [8192,4096]
__device__ __align__(1024) float g_t [8388608];   // t = x @ V^T     [8192,1024]
__device__ __align__(1024) float g_Us[4194304];   // (U cat)*s, tf32 [4096,1024]
__device__ __align__(1024) float g_V [4194304];   // V cat, tf32     [1024,4096]

// ---------------- helpers ----------------
__device__ __forceinline__ float tf32r(float x) {
    uint32_t u; asm("cvt.rna.tf32.f32 %0, %1;" : "=r"(u) : "f"(x));
    return __uint_as_float(u);
}
__device__ __forceinline__ void cp16(uint32_t s, const float* g) {
    asm volatile("cp.async.cg.shared.global [%0], [%1], 16;" :: "r"(s), "l"(g));
}
__device__ __forceinline__ void mma8(float* c, const uint32_t* a, const uint32_t* b) {
    asm volatile("mma.sync.aligned.m16n8k8.row.col.f32.tf32.tf32.f32 "
                 "{%0,%1,%2,%3}, {%4,%5,%6,%7}, {%8,%9}, {%0,%1,%2,%3};"
                 : "+f"(c[0]), "+f"(c[1]), "+f"(c[2]), "+f"(c[3])
                 : "r"(a[0]), "r"(a[1]), "r"(a[2]), "r"(a[3]),
                   "r"(b[0]), "r"(b[1]));
}

// ---------------- pack: Us=(cat U)*s, V=cat(V), x -> tf32 (all RNA-rounded) ----------------
#define US_F4 1048576
#define V_F4  1048576
#define X_F4  8388608
__global__ void pack_cvt(const float* __restrict__ x,
                         const float* __restrict__ u_t, const float* __restrict__ u_d,
                         const float* __restrict__ s,
                         const float* __restrict__ v_t, const float* __restrict__ v_d)
{
    int t = blockIdx.x * blockDim.x + threadIdx.x;
    if (t < US_F4) {
        int o = t >> 8, r4 = t & 255;
        float4 u = (r4 < 16) ? *(const float4*)(u_t + o * 64 + r4 * 4)
                             : *(const float4*)(u_d + o * 960 + r4 * 4 - 64);
        float4 sv = *(const float4*)(s + r4 * 4);
        *(float4*)(g_Us + (size_t)t * 4) =
            make_float4(tf32r(u.x * sv.x), tf32r(u.y * sv.y),
                        tf32r(u.z * sv.z), tf32r(u.w * sv.w));
    } else if (t < US_F4 + V_F4) {
        int j = t - US_F4;
        int r = j >> 10;
        float4 v = (r < 64) ? *(const float4*)(v_t + (size_t)j * 4)
                            : *(const float4*)(v_d + (size_t)j * 4 - 64 * 4096);
        *(float4*)(g_V + (size_t)j * 4) =
            make_float4(tf32r(v.x), tf32r(v.y), tf32r(v.z), tf32r(v.w));
    } else {
        size_t i = (size_t)(t - US_F4 - V_F4) * 4;
        float4 v = *(const float4*)(x + i);
        *(float4*)(g_xt + i) =
            make_float4(tf32r(v.x), tf32r(v.y), tf32r(v.z), tf32r(v.w));
    }
}

// ---------------- TF32 mma.sync GEMM: C[M,N] = A[M,K] @ B[N,K]^T (+bias) ----------------
template<bool BIAS, bool ROUND>
__global__ void __launch_bounds__(256, 2)
gemm_mma(const float* __restrict__ A, const float* __restrict__ Bm,
         const float* __restrict__ bias, float* __restrict__ C,
         int N, int K)
{
    extern __shared__ __align__(16) float sm[];
    const int tid  = threadIdx.x;
    const int lane = tid & 31;
    const int wid  = tid >> 5;
    const int wm   = wid >> 2;          // 0..1  (64-row warp band)
    const int wn   = wid & 3;           // 0..3  (32-col warp band)
    const int g    = lane >> 2;         // group id 0..7
    const int tg   = lane & 3;          // thread-in-group

    const int mBase = blockIdx.y * BM;
    const int nBase = blockIdx.x * BN;
    const float* Ag = A  + (size_t)mBase * K;
    const float* Bg = Bm + (size_t)nBase * K;

    const int lr = tid >> 2;            // load row 0..63
    const int lc = (tid & 3) * 4;       // load col 0,4,8,12

    const uint32_t sbase = (uint32_t)__cvta_generic_to_shared(sm);

    float c[4][4][4];
#pragma unroll
    for (int mt = 0; mt < 4; mt++)
#pragma unroll
        for (int nt = 0; nt < 4; nt++)
#pragma unroll
            for (int i = 0; i < 4; i++) c[mt][nt][i] = 0.f;

    auto load_stage = [&](int s, int kt) {
        const uint32_t aS = sbase + (uint32_t)(s * STAGE_FLOATS) * 4u;
        const uint32_t bS = aS + (uint32_t)AS_FLOATS * 4u;
        const float* Ap = Ag + (size_t)lr * K + kt * BK + lc;
        const float* Bp = Bg + (size_t)lr * K + kt * BK + lc;
        cp16(aS + (uint32_t)(lr * SA + lc) * 4u,        Ap);
        cp16(aS + (uint32_t)((lr + 64) * SA + lc) * 4u, Ap + (size_t)64 * K);
        cp16(bS + (uint32_t)(lr * SA + lc) * 4u,        Bp);
        cp16(bS + (uint32_t)((lr + 64) * SA + lc) * 4u, Bp + (size_t)64 * K);
        asm volatile("cp.async.commit_group;" ::: "memory");
    };

#pragma unroll
    for (int s = 0; s < STAGES - 1; s++) load_stage(s, s);

    const int KT = K / BK;
    for (int kt = 0; kt < KT; kt++) {
        asm volatile("cp.async.wait_group %0;" :: "n"(STAGES - 2) : "memory");
        __syncthreads();

        const int pf = kt + STAGES - 1;
        if (pf < KT) load_stage(pf & (STAGES - 1), pf);
        else asm volatile("cp.async.commit_group;" ::: "memory");

        const float* As_ = sm + (kt & (STAGES - 1)) * STAGE_FLOATS;
        const float* Bs_ = As_ + AS_FLOATS;

#pragma unroll
        for (int kk = 0; kk < BK; kk += 8) {
            uint32_t a[4][4], b[4][2];
#pragma unroll
            for (int mt = 0; mt < 4; mt++) {
                const float* p = As_ + (wm * 64 + mt * 16 + g) * SA + kk + tg;
                a[mt][0] = __float_as_uint(p[0]);
                a[mt][1] = __float_as_uint(p[8 * SA]);
                a[mt][2] = __float_as_uint(p[4]);
                a[mt][3] = __float_as_uint(p[8 * SA + 4]);
            }
#pragma unroll
            for (int nt = 0; nt < 4; nt++) {
                const float* p = Bs_ + (wn * 32 + nt * 8 + g) * SA + kk + tg;
                b[nt][0] = __float_as_uint(p[0]);
                b[nt][1] = __float_as_uint(p[4]);
            }
#pragma unroll
            for (int mt = 0; mt < 4; mt++)
#pragma unroll
                for (int nt = 0; nt < 4; nt++)
                    mma8(c[mt][nt], a[mt], b[nt]);
        }
    }

    // ---- epilogue ----
#pragma unroll
    for (int mt = 0; mt < 4; mt++) {
        const int row = mBase + wm * 64 + mt * 16 + g;
#pragma unroll
        for (int nt = 0; nt < 4; nt++) {
            const int col = nBase + wn * 32 + nt * 8 + 2 * tg;
            float2 v0 = make_float2(c[mt][nt][0], c[mt][nt][1]);
            float2 v1 = make_float2(c[mt][nt][2], c[mt][nt][3]);
            if (BIAS) {
                float b0 = bias[col], b1 = bias[col + 1];
                v0.x += b0; v0.y += b1; v1.x += b0; v1.y += b1;
            }
            if (ROUND) {
                v0.x = tf32r(v0.x); v0.y = tf32r(v0.y);
                v1.x = tf32r(v1.x); v1.y = tf32r(v1.y);
            }
            *(float2*)(C + (size_t)row * N + col)       = v0;
            *(float2*)(C + (size_t)(row + 8) * N + col) = v1;
        }
    }
}

// ---------------- host ----------------
extern "C" void kernel_launch(void* const* d_in, const int* in_sizes, int n_in,
                              void* d_out, int out_size)
{
    const float* x    = (const float*)d_in[0];   // [4,2048,4096]
    const float* u_t  = (const float*)d_in[1];   // [4096,64]
    const float* u_d  = (const float*)d_in[2];   // [4096,960]
    const float* s    = (const float*)d_in[3];   // [1024]
    const float* v_t  = (const float*)d_in[4];   // [64,4096]
    const float* v_d  = (const float*)d_in[5];   // [960,4096]
    const float* bias = (const float*)d_in[6];   // [4096]
    float* out = (float*)d_out;                  // [4,2048,4096]
    (void)in_sizes; (void)n_in; (void)out_size;

    float *xt, *tbuf, *Us;
    cudaGetSymbolAddress((void**)&xt,   g_xt);
    cudaGetSymbolAddress((void**)&tbuf, g_t);
    cudaGetSymbolAddress((void**)&Us,   g_Us);
    float* V;
    cudaGetSymbolAddress((void**)&V,    g_V);

    cudaFuncSetAttribute(gemm_mma<false, true>,
                         cudaFuncAttributeMaxDynamicSharedMemorySize, SMEM_BYTES);
    cudaFuncSetAttribute(gemm_mma<true, false>,
                         cudaFuncAttributeMaxDynamicSharedMemorySize, SMEM_BYTES);

    // 1) pack + tf32-round
    pack_cvt<<<(US_F4 + V_F4 + X_F4) / 256, 256>>>(x, u_t, u_d, s, v_t, v_d);

    // 2) t = x_t @ V^T   (M=8192, N=1024, K=4096); epilogue rounds t to tf32
    gemm_mma<false, true><<<dim3(1024 / BN, 8192 / BM), 256, SMEM_BYTES>>>(
        xt, V, nullptr, tbuf, 1024, 4096);

    // 3) out = t @ Us^T + bias  (M=8192, N=4096, K=1024)
    gemm_mma<true, false><<<dim3(4096 / BN, 8192 / BM), 256, SMEM_BYTES>>>(
        tbuf, Us, bias, out, 4096, 1024);
}

// round 4
// speedup vs baseline: 5.6198x; 2.2990x over previous
#include <cuda_runtime.h>
#include <cuda_fp16.h>
#include <cstdint>

// ---------------- tiles ----------------
#define BM 128
#define BN 128
#define BK 32
#define STAGES 4
#define ROWB 80                                   // bytes per smem row (32 halfs + 8 pad)
#define A_STAGE_B (BM * ROWB)                     // 10240
#define STAGE_B   (2 * A_STAGE_B)                 // 20480
#define SMEM_BYTES (STAGES * STAGE_B)             // 81920

// ---------------- scratch (allocation-free rule) ----------------
__device__ __align__(1024) __half g_xt[33554432]; // x  -> fp16   [8192,4096]
__device__ __align__(1024) __half g_t [8388608];  // t = x @ V^T  [8192,1024]
__device__ __align__(1024) __half g_Us[4194304];  // (U cat)*s    [4096,1024]
__device__ __align__(1024) __half g_V [4194304];  // V cat        [1024,4096]

// ---------------- helpers ----------------
__device__ __forceinline__ void cp16(uint32_t s, const void* g) {
    asm volatile("cp.async.cg.shared.global [%0], [%1], 16;" :: "r"(s), "l"(g));
}
__device__ __forceinline__ void ldsm4(uint32_t* r, uint32_t addr) {
    asm volatile("ldmatrix.sync.aligned.m8n8.x4.shared.b16 {%0,%1,%2,%3}, [%4];"
                 : "=r"(r[0]), "=r"(r[1]), "=r"(r[2]), "=r"(r[3]) : "r"(addr));
}
__device__ __forceinline__ void mma16(float* c, const uint32_t* a, const uint32_t* b) {
    asm volatile("mma.sync.aligned.m16n8k16.row.col.f32.f16.f16.f32 "
                 "{%0,%1,%2,%3}, {%4,%5,%6,%7}, {%8,%9}, {%0,%1,%2,%3};"
                 : "+f"(c[0]), "+f"(c[1]), "+f"(c[2]), "+f"(c[3])
                 : "r"(a[0]), "r"(a[1]), "r"(a[2]), "r"(a[3]),
                   "r"(b[0]), "r"(b[1]));
}

// ---------------- pack: Us=(cat U)*s, V=cat V, x — all -> fp16 RN ----------------
#define US_F4 1048576
#define V_F4  1048576
#define X_F4  8388608
__global__ void pack_cvt(const float* __restrict__ x,
                         const float* __restrict__ u_t, const float* __restrict__ u_d,
                         const float* __restrict__ s,
                         const float* __restrict__ v_t, const float* __restrict__ v_d)
{
    int t = blockIdx.x * blockDim.x + threadIdx.x;
    if (t < US_F4) {
        int o = t >> 8, r4 = t & 255;
        float4 u = (r4 < 16) ? *(const float4*)(u_t + o * 64 + r4 * 4)
                             : *(const float4*)(u_d + o * 960 + r4 * 4 - 64);
        float4 sv = *(const float4*)(s + r4 * 4);
        __half2 h0 = __float22half2_rn(make_float2(u.x * sv.x, u.y * sv.y));
        __half2 h1 = __float22half2_rn(make_float2(u.z * sv.z, u.w * sv.w));
        *(uint2*)(g_Us + (size_t)t * 4) =
            make_uint2(*(uint32_t*)&h0, *(uint32_t*)&h1);
    } else if (t < US_F4 + V_F4) {
        int j = t - US_F4;
        int r = j >> 10;
        float4 v = (r < 64) ? *(const float4*)(v_t + (size_t)j * 4)
                            : *(const float4*)(v_d + (size_t)j * 4 - 64 * 4096);
        __half2 h0 = __float22half2_rn(make_float2(v.x, v.y));
        __half2 h1 = __float22half2_rn(make_float2(v.z, v.w));
        *(uint2*)(g_V + (size_t)j * 4) =
            make_uint2(*(uint32_t*)&h0, *(uint32_t*)&h1);
    } else {
        size_t i = (size_t)(t - US_F4 - V_F4) * 4;
        float4 v = *(const float4*)(x + i);
        __half2 h0 = __float22half2_rn(make_float2(v.x, v.y));
        __half2 h1 = __float22half2_rn(make_float2(v.z, v.w));
        *(uint2*)(g_xt + i) =
            make_uint2(*(uint32_t*)&h0, *(uint32_t*)&h1);
    }
}

// ---------------- fp16 mma GEMM: C[M,N] = A[M,K] @ B[N,K]^T (+bias) ----------------
// A,B fp16 K-contiguous. HALF_OUT: store fp16 (for t); else fp32 (+bias).
template<bool HALF_OUT>
__global__ void __launch_bounds__(128, 2)
gemm_h(const __half* __restrict__ A, const __half* __restrict__ Bm,
       const float* __restrict__ bias, void* __restrict__ Cout,
       int N, int K)
{
    extern __shared__ __align__(16) char sm[];
    const uint32_t sbase = (uint32_t)__cvta_generic_to_shared(sm);
    const int tid  = threadIdx.x;
    const int lane = tid & 31;
    const int wid  = tid >> 5;
    const int wm   = wid >> 1;          // 0..1  row band (64)
    const int wn   = wid & 1;           // 0..1  col band (64)
    const int g    = lane >> 2;
    const int tg   = lane & 3;

    const int mBase = blockIdx.y * BM;
    const int nBase = blockIdx.x * BN;
    const __half* Ag = A  + (size_t)mBase * K;
    const __half* Bg = Bm + (size_t)nBase * K;

    // cp.async mapping: 4 chunks each for A and B per stage per thread
    const int lr0 = tid >> 2;           // 0..31 (+32*i)
    const int lcB = (tid & 3) * 16;     // byte col 0,16,32,48

    // ldmatrix per-lane byte offsets (within A/B region of a stage)
    const int aRow = wm * 64 + (lane & 7) + ((lane >> 3) & 1) * 8;
    const int aKb  = (lane >> 4) * 16;                 // k offset bytes (0/16)
    const uint32_t aOff = (uint32_t)(aRow * ROWB + aKb);
    const int bRow = wn * 64 + (lane & 7) + (lane >> 4) * 8;
    const int bKb  = ((lane >> 3) & 1) * 16;
    const uint32_t bOff = (uint32_t)(bRow * ROWB + bKb) + A_STAGE_B;

    float c[4][8][4];
#pragma unroll
    for (int mt = 0; mt < 4; mt++)
#pragma unroll
        for (int nt = 0; nt < 8; nt++)
#pragma unroll
            for (int i = 0; i < 4; i++) c[mt][nt][i] = 0.f;

    auto load_stage = [&](int st, int kt) {
        const uint32_t base = sbase + (uint32_t)st * STAGE_B;
#pragma unroll
        for (int i = 0; i < 4; i++) {
            const int row = lr0 + 32 * i;
            cp16(base + (uint32_t)(row * ROWB) + lcB,
                 (const char*)(Ag + (size_t)row * K + kt * BK) + lcB);
            cp16(base + A_STAGE_B + (uint32_t)(row * ROWB) + lcB,
                 (const char*)(Bg + (size_t)row * K + kt * BK) + lcB);
        }
        asm volatile("cp.async.commit_group;" ::: "memory");
    };

#pragma unroll
    for (int s = 0; s < STAGES - 1; s++) load_stage(s, s);

    const int KT = K / BK;
    for (int kt = 0; kt < KT; kt++) {
        asm volatile("cp.async.wait_group %0;" :: "n"(STAGES - 2) : "memory");
        __syncthreads();

        const uint32_t stBase = sbase + (uint32_t)(kt & (STAGES - 1)) * STAGE_B;

#pragma unroll
        for (int kk = 0; kk < 2; kk++) {            // two k16 per BK=32
            const uint32_t kByte = (uint32_t)(kk * 32);
            uint32_t a[4][4];
#pragma unroll
            for (int mt = 0; mt < 4; mt++)
                ldsm4(a[mt], stBase + aOff + (uint32_t)(mt * 16 * ROWB) + kByte);
#pragma unroll
            for (int np = 0; np < 4; np++) {
                uint32_t b[4];
                ldsm4(b, stBase + bOff + (uint32_t)(np * 16 * ROWB) + kByte);
#pragma unroll
                for (int mt = 0; mt < 4; mt++) {
                    mma16(c[mt][np * 2],     a[mt], b);
                    mma16(c[mt][np * 2 + 1], a[mt], b + 2);
                }
            }
        }
        __syncthreads();

        const int pf = kt + STAGES - 1;
        if (pf < KT) load_stage(pf & (STAGES - 1), pf);
        else asm volatile("cp.async.commit_group;" ::: "memory");
    }

    // ---- epilogue ----
#pragma unroll
    for (int mt = 0; mt < 4; mt++) {
        const int row = mBase + wm * 64 + mt * 16 + g;
#pragma unroll
        for (int nt = 0; nt < 8; nt++) {
            const int col = nBase + wn * 64 + nt * 8 + 2 * tg;
            if (HALF_OUT) {
                __half* C = (__half*)Cout;
                *(__half2*)(C + (size_t)row * N + col) =
                    __float22half2_rn(make_float2(c[mt][nt][0], c[mt][nt][1]));
                *(__half2*)(C + (size_t)(row + 8) * N + col) =
                    __float22half2_rn(make_float2(c[mt][nt][2], c[mt][nt][3]));
            } else {
                float* C = (float*)Cout;
                const float b0 = bias[col], b1 = bias[col + 1];
                *(float2*)(C + (size_t)row * N + col) =
                    make_float2(c[mt][nt][0] + b0, c[mt][nt][1] + b1);
                *(float2*)(C + (size_t)(row + 8) * N + col) =
                    make_float2(c[mt][nt][2] + b0, c[mt][nt][3] + b1);
            }
        }
    }
}

// ---------------- host ----------------
extern "C" void kernel_launch(void* const* d_in, const int* in_sizes, int n_in,
                              void* d_out, int out_size)
{
    const float* x    = (const float*)d_in[0];   // [4,2048,4096]
    const float* u_t  = (const float*)d_in[1];   // [4096,64]
    const float* u_d  = (const float*)d_in[2];   // [4096,960]
    const float* s    = (const float*)d_in[3];   // [1024]
    const float* v_t  = (const float*)d_in[4];   // [64,4096]
    const float* v_d  = (const float*)d_in[5];   // [960,4096]
    const float* bias = (const float*)d_in[6];   // [4096]
    float* out = (float*)d_out;                  // [4,2048,4096]
    (void)in_sizes; (void)n_in; (void)out_size;

    __half *xt, *tbuf, *Us, *V;
    cudaGetSymbolAddress((void**)&xt,   g_xt);
    cudaGetSymbolAddress((void**)&tbuf, g_t);
    cudaGetSymbolAddress((void**)&Us,   g_Us);
    cudaGetSymbolAddress((void**)&V,    g_V);

    cudaFuncSetAttribute(gemm_h<true>,
                         cudaFuncAttributeMaxDynamicSharedMemorySize, SMEM_BYTES);
    cudaFuncSetAttribute(gemm_h<false>,
                         cudaFuncAttributeMaxDynamicSharedMemorySize, SMEM_BYTES);

    // 1) pack + fp16 conversion
    pack_cvt<<<(US_F4 + V_F4 + X_F4) / 256, 256>>>(x, u_t, u_d, s, v_t, v_d);

    // 2) t = x @ V^T     (M=8192, N=1024, K=4096), fp16 out
    gemm_h<true><<<dim3(1024 / BN, 8192 / BM), 128, SMEM_BYTES>>>(
        xt, V, nullptr, tbuf, 1024, 4096);

    // 3) out = t @ Us^T + bias  (M=8192, N=4096, K=1024), fp32 out
    gemm_h<false><<<dim3(4096 / BN, 8192 / BM), 128, SMEM_BYTES>>>(
        tbuf, Us, bias, out, 4096, 1024);
}

// round 5
// speedup vs baseline: 5.7769x; 1.0280x over previous
#include <cuda_runtime.h>
#include <cuda_fp16.h>
#include <cstdint>

// ---------------- tiles ----------------
#define BM 128
#define BN 128
#define BK 64
#define STAGES 3
#define ROWB 144                                  // 64 halfs (128B) + 16B pad; 9*16B -> conflict-free LDSM
#define A_STAGE_B (BM * ROWB)                     // 18432
#define STAGE_B   (2 * A_STAGE_B)                 // 36864
#define SMEM_BYTES (STAGES * STAGE_B)             // 110592 (2 CTAs/SM = 216KB)

// ---------------- scratch (allocation-free rule) ----------------
__device__ __align__(1024) __half g_xt[33554432]; // x  -> fp16   [8192,4096]
__device__ __align__(1024) __half g_t [8388608];  // t = x @ V^T  [8192,1024]
__device__ __align__(1024) __half g_Us[4194304];  // (U cat)*s    [4096,1024]
__device__ __align__(1024) __half g_V [4194304];  // V cat        [1024,4096]

// ---------------- helpers ----------------
__device__ __forceinline__ void cp16(uint32_t s, const void* g) {
    asm volatile("cp.async.cg.shared.global [%0], [%1], 16;" :: "r"(s), "l"(g));
}
__device__ __forceinline__ void ldsm4(uint32_t* r, uint32_t addr) {
    asm volatile("ldmatrix.sync.aligned.m8n8.x4.shared.b16 {%0,%1,%2,%3}, [%4];"
                 : "=r"(r[0]), "=r"(r[1]), "=r"(r[2]), "=r"(r[3]) : "r"(addr));
}
__device__ __forceinline__ void mma16(float* c, const uint32_t* a, const uint32_t* b) {
    asm volatile("mma.sync.aligned.m16n8k16.row.col.f32.f16.f16.f32 "
                 "{%0,%1,%2,%3}, {%4,%5,%6,%7}, {%8,%9}, {%0,%1,%2,%3};"
                 : "+f"(c[0]), "+f"(c[1]), "+f"(c[2]), "+f"(c[3])
                 : "r"(a[0]), "r"(a[1]), "r"(a[2]), "r"(a[3]),
                   "r"(b[0]), "r"(b[1]));
}

// ---------------- pack: Us=(cat U)*s, V=cat V, x — all -> fp16 RN ----------------
#define US_F4 1048576
#define V_F4  1048576
#define X_F4  8388608
__global__ void pack_cvt(const float* __restrict__ x,
                         const float* __restrict__ u_t, const float* __restrict__ u_d,
                         const float* __restrict__ s,
                         const float* __restrict__ v_t, const float* __restrict__ v_d)
{
    int t = blockIdx.x * blockDim.x + threadIdx.x;
    if (t < US_F4) {
        int o = t >> 8, r4 = t & 255;
        float4 u = (r4 < 16) ? *(const float4*)(u_t + o * 64 + r4 * 4)
                             : *(const float4*)(u_d + o * 960 + r4 * 4 - 64);
        float4 sv = *(const float4*)(s + r4 * 4);
        __half2 h0 = __float22half2_rn(make_float2(u.x * sv.x, u.y * sv.y));
        __half2 h1 = __float22half2_rn(make_float2(u.z * sv.z, u.w * sv.w));
        *(uint2*)(g_Us + (size_t)t * 4) = make_uint2(*(uint32_t*)&h0, *(uint32_t*)&h1);
    } else if (t < US_F4 + V_F4) {
        int j = t - US_F4;
        int r = j >> 10;
        float4 v = (r < 64) ? *(const float4*)(v_t + (size_t)j * 4)
                            : *(const float4*)(v_d + (size_t)j * 4 - 64 * 4096);
        __half2 h0 = __float22half2_rn(make_float2(v.x, v.y));
        __half2 h1 = __float22half2_rn(make_float2(v.z, v.w));
        *(uint2*)(g_V + (size_t)j * 4) = make_uint2(*(uint32_t*)&h0, *(uint32_t*)&h1);
    } else {
        size_t i = (size_t)(t - US_F4 - V_F4) * 4;
        float4 v = *(const float4*)(x + i);
        __half2 h0 = __float22half2_rn(make_float2(v.x, v.y));
        __half2 h1 = __float22half2_rn(make_float2(v.z, v.w));
        *(uint2*)(g_xt + i) = make_uint2(*(uint32_t*)&h0, *(uint32_t*)&h1);
    }
}

// ---------------- fp16 mma GEMM: C[M,N] = A[M,K] @ B[N,K]^T (+bias) ----------------
template<bool HALF_OUT>
__global__ void __launch_bounds__(128, 2)
gemm_h(const __half* __restrict__ A, const __half* __restrict__ Bm,
       const float* __restrict__ bias, void* __restrict__ Cout,
       int N, int K)
{
    extern __shared__ __align__(16) char sm[];
    const uint32_t sbase = (uint32_t)__cvta_generic_to_shared(sm);
    const int tid  = threadIdx.x;
    const int lane = tid & 31;
    const int wid  = tid >> 5;
    const int wm   = wid >> 1;          // 0..1 row band (64)
    const int wn   = wid & 1;           // 0..1 col band (64)
    const int g    = lane >> 2;
    const int tg   = lane & 3;

    const int mBase = blockIdx.y * BM;
    const int nBase = blockIdx.x * BN;
    const __half* Ag = A  + (size_t)mBase * K;
    const __half* Bg = Bm + (size_t)nBase * K;

    // ldmatrix per-lane offsets within stage
    const int aRow = wm * 64 + (lane & 7) + ((lane >> 3) & 1) * 8;
    const int aKb  = (lane >> 4) * 16;
    const uint32_t aOff = (uint32_t)(aRow * ROWB + aKb);
    const int bRow = wn * 64 + (lane & 7) + (lane >> 4) * 8;
    const int bKb  = ((lane >> 3) & 1) * 16;
    const uint32_t bOff = (uint32_t)(bRow * ROWB + bKb) + A_STAGE_B;

    float c[4][8][4];
#pragma unroll
    for (int mt = 0; mt < 4; mt++)
#pragma unroll
        for (int nt = 0; nt < 8; nt++)
#pragma unroll
            for (int i = 0; i < 4; i++) c[mt][nt][i] = 0.f;

    // loads: 8 A-chunks + 8 B-chunks of 16B per thread per stage, warp-coalesced
    auto load_stage = [&](int st, int kt) {
        const uint32_t base = sbase + (uint32_t)st * STAGE_B;
        const size_t kOff = (size_t)kt * BK;
#pragma unroll
        for (int i = 0; i < 8; i++) {
            const int cid = i * 128 + tid;          // 0..1023
            const int row = cid >> 3;
            const uint32_t colB = (uint32_t)(cid & 7) * 16u;
            cp16(base + (uint32_t)(row * ROWB) + colB,
                 (const char*)(Ag + (size_t)row * K + kOff) + colB);
            cp16(base + A_STAGE_B + (uint32_t)(row * ROWB) + colB,
                 (const char*)(Bg + (size_t)row * K + kOff) + colB);
        }
        asm volatile("cp.async.commit_group;" ::: "memory");
    };

#pragma unroll
    for (int s = 0; s < STAGES - 1; s++) load_stage(s, s);

    const int KT = K / BK;
    for (int kt = 0; kt < KT; kt++) {
        asm volatile("cp.async.wait_group %0;" :: "n"(STAGES - 2) : "memory");
        __syncthreads();

        const int pf = kt + STAGES - 1;
        if (pf < KT) load_stage(pf % STAGES, pf);
        else asm volatile("cp.async.commit_group;" ::: "memory");

        const uint32_t stBase = sbase + (uint32_t)(kt % STAGES) * STAGE_B;

#pragma unroll
        for (int kk = 0; kk < BK / 16; kk++) {
            const uint32_t kByte = (uint32_t)(kk * 32);
            uint32_t a[4][4];
#pragma unroll
            for (int mt = 0; mt < 4; mt++)
                ldsm4(a[mt], stBase + aOff + (uint32_t)(mt * 16 * ROWB) + kByte);
#pragma unroll
            for (int np = 0; np < 4; np++) {
                uint32_t b[4];
                ldsm4(b, stBase + bOff + (uint32_t)(np * 16 * ROWB) + kByte);
#pragma unroll
                for (int mt = 0; mt < 4; mt++) {
                    mma16(c[mt][np * 2],     a[mt], b);
                    mma16(c[mt][np * 2 + 1], a[mt], b + 2);
                }
            }
        }
    }

    // ---- epilogue ----
#pragma unroll
    for (int mt = 0; mt < 4; mt++) {
        const int row = mBase + wm * 64 + mt * 16 + g;
#pragma unroll
        for (int nt = 0; nt < 8; nt++) {
            const int col = nBase + wn * 64 + nt * 8 + 2 * tg;
            if (HALF_OUT) {
                __half* C = (__half*)Cout;
                *(__half2*)(C + (size_t)row * N + col) =
                    __float22half2_rn(make_float2(c[mt][nt][0], c[mt][nt][1]));
                *(__half2*)(C + (size_t)(row + 8) * N + col) =
                    __float22half2_rn(make_float2(c[mt][nt][2], c[mt][nt][3]));
            } else {
                float* C = (float*)Cout;
                const float b0 = bias[col], b1 = bias[col + 1];
                *(float2*)(C + (size_t)row * N + col) =
                    make_float2(c[mt][nt][0] + b0, c[mt][nt][1] + b1);
                *(float2*)(C + (size_t)(row + 8) * N + col) =
                    make_float2(c[mt][nt][2] + b0, c[mt][nt][3] + b1);
            }
        }
    }
}

// ---------------- host ----------------
extern "C" void kernel_launch(void* const* d_in, const int* in_sizes, int n_in,
                              void* d_out, int out_size)
{
    const float* x    = (const float*)d_in[0];
    const float* u_t  = (const float*)d_in[1];
    const float* u_d  = (const float*)d_in[2];
    const float* s    = (const float*)d_in[3];
    const float* v_t  = (const float*)d_in[4];
    const float* v_d  = (const float*)d_in[5];
    const float* bias = (const float*)d_in[6];
    float* out = (float*)d_out;
    (void)in_sizes; (void)n_in; (void)out_size;

    __half *xt, *tbuf, *Us, *V;
    cudaGetSymbolAddress((void**)&xt,   g_xt);
    cudaGetSymbolAddress((void**)&tbuf, g_t);
    cudaGetSymbolAddress((void**)&Us,   g_Us);
    cudaGetSymbolAddress((void**)&V,    g_V);

    cudaFuncSetAttribute(gemm_h<true>,
                         cudaFuncAttributeMaxDynamicSharedMemorySize, SMEM_BYTES);
    cudaFuncSetAttribute(gemm_h<false>,
                         cudaFuncAttributeMaxDynamicSharedMemorySize, SMEM_BYTES);

    // 1) pack + fp16 conversion
    pack_cvt<<<(US_F4 + V_F4 + X_F4) / 256, 256>>>(x, u_t, u_d, s, v_t, v_d);

    // 2) t = x @ V^T     (M=8192, N=1024, K=4096), fp16 out
    gemm_h<true><<<dim3(1024 / BN, 8192 / BM), 128, SMEM_BYTES>>>(
        xt, V, nullptr, tbuf, 1024, 4096);

    // 3) out = t @ Us^T + bias  (M=8192, N=4096, K=1024), fp32 out
    gemm_h<false><<<dim3(4096 / BN, 8192 / BM), 128, SMEM_BYTES>>>(
        tbuf, Us, bias, out, 4096, 1024);
}